// round 3
// baseline (speedup 1.0000x reference)
#include <cuda_runtime.h>

// 8x8 IDCT, separable + even/odd symmetry, TWO blocks' rows per thread for MLP.
//   out = 0.25 * M^T * S * M + 128,  M[y][v] = a[y]*cos((2v+1)*y*pi/16)
// Thread handles row (base+tid) and row (base+256+tid): 4 independent LDG.128
// front-batched -> doubles memory-level parallelism vs 1-row/thread.
// Per row: even/odd row pass -> 8x8 register transpose (shfl.bfly within the
// 8-lane group) -> even/odd column pass (0.25/+128 folded in) -> direct
// column-order scalar stores (lane p owns output column p).

#define FULLMASK 0xFFFFFFFFu

__device__ __forceinline__ void transpose8(float v[8], int r) {
#pragma unroll
    for (int m = 1; m < 8; m <<= 1) {
#pragma unroll
        for (int i = 0; i < 8; i++) {
            if (i & m) continue;
            const int j = i | m;
            const bool up = (r & m) != 0;
            float send = up ? v[i] : v[j];
            float recv = __shfl_xor_sync(FULLMASK, send, m);
            if (up) v[i] = recv; else v[j] = recv;
        }
    }
}

struct RowCtx {
    // Even rows of M (y=0,2,4,6), cols v=0..3 / odd rows (y=1,3,5,7).
    float ME[4][4];
    float MO[4][4];
};

__device__ __forceinline__ void idct_row_pass(const float s[8], float acc[8]) {
    const float ME[4][4] = {
        { 0.70710678f,  0.70710678f,  0.70710678f,  0.70710678f },
        { 0.92387953f,  0.38268343f, -0.38268343f, -0.92387953f },
        { 0.70710678f, -0.70710678f, -0.70710678f,  0.70710678f },
        { 0.38268343f, -0.92387953f,  0.92387953f, -0.38268343f },
    };
    const float MO[4][4] = {
        { 0.98078528f,  0.83146961f,  0.55557023f,  0.19509032f },
        { 0.83146961f, -0.19509032f, -0.98078528f, -0.55557023f },
        { 0.55557023f, -0.98078528f,  0.19509032f,  0.83146961f },
        { 0.19509032f, -0.55557023f,  0.83146961f, -0.98078528f },
    };
#pragma unroll
    for (int v = 0; v < 4; v++) {
        float e = s[0] * ME[0][v];
        e = fmaf(s[2], ME[1][v], e);
        e = fmaf(s[4], ME[2][v], e);
        e = fmaf(s[6], ME[3][v], e);
        float o = s[1] * MO[0][v];
        o = fmaf(s[3], MO[1][v], o);
        o = fmaf(s[5], MO[2][v], o);
        o = fmaf(s[7], MO[3][v], o);
        acc[v]     = e + o;
        acc[7 - v] = e - o;
    }
}

__device__ __forceinline__ void idct_col_pass(const float acc[8], float o[8]) {
    const float ME[4][4] = {
        { 0.70710678f,  0.70710678f,  0.70710678f,  0.70710678f },
        { 0.92387953f,  0.38268343f, -0.38268343f, -0.92387953f },
        { 0.70710678f, -0.70710678f, -0.70710678f,  0.70710678f },
        { 0.38268343f, -0.92387953f,  0.92387953f, -0.38268343f },
    };
    const float MO[4][4] = {
        { 0.98078528f,  0.83146961f,  0.55557023f,  0.19509032f },
        { 0.83146961f, -0.19509032f, -0.98078528f, -0.55557023f },
        { 0.55557023f, -0.98078528f,  0.19509032f,  0.83146961f },
        { 0.19509032f, -0.55557023f,  0.83146961f, -0.98078528f },
    };
#pragma unroll
    for (int u = 0; u < 4; u++) {
        float e = fmaf(acc[0], 0.25f * ME[0][u], 128.0f);
        e = fmaf(acc[2], 0.25f * ME[1][u], e);
        e = fmaf(acc[4], 0.25f * ME[2][u], e);
        e = fmaf(acc[6], 0.25f * ME[3][u], e);
        float od = acc[1] * (0.25f * MO[0][u]);
        od = fmaf(acc[3], 0.25f * MO[1][u], od);
        od = fmaf(acc[5], 0.25f * MO[2][u], od);
        od = fmaf(acc[7], 0.25f * MO[3][u], od);
        o[u]     = e + od;
        o[7 - u] = e - od;
    }
}

__global__ void __launch_bounds__(256)
idct_54271206752953_kernel(const float* __restrict__ in,
                           float* __restrict__ out,
                           int n_rows) {
    const int tid = threadIdx.x;
    const int r = tid & 7;
    // Each 256-thread block owns 512 consecutive rows: [base, base+512).
    const int base = blockIdx.x * 512;
    const int t0 = base + tid;
    const int t1 = base + 256 + tid;

    // Front-batch all 4 independent LDG.128 (MLP = 4).
    const float4* in4 = reinterpret_cast<const float4*>(in);
    float4 a0 = in4[(size_t)t0 * 2 + 0];
    float4 a1 = in4[(size_t)t0 * 2 + 1];
    float4 b0 = in4[(size_t)t1 * 2 + 0];
    float4 b1 = in4[(size_t)t1 * 2 + 1];

    float sA[8] = { a0.x, a0.y, a0.z, a0.w, a1.x, a1.y, a1.z, a1.w };
    float sB[8] = { b0.x, b0.y, b0.z, b0.w, b1.x, b1.y, b1.z, b1.w };

    float accA[8], accB[8];
    idct_row_pass(sA, accA);
    idct_row_pass(sB, accB);

    // Two independent transpose chains -> shfl latency overlaps.
    transpose8(accA, r);
    transpose8(accB, r);

    float oA[8], oB[8];
    idct_col_pass(accA, oA);
    idct_col_pass(accB, oB);

    // Lane p holds output COLUMN p of its block. Warp-level each scalar store
    // covers complete 32B sectors (8 contiguous lanes x 4 blocks).
    float* opA = out + ((size_t)(t0 >> 3)) * 64 + r;
    float* opB = out + ((size_t)(t1 >> 3)) * 64 + r;
#pragma unroll
    for (int u = 0; u < 8; u++) opA[u * 8] = oA[u];
#pragma unroll
    for (int u = 0; u < 8; u++) opB[u * 8] = oB[u];
}

extern "C" void kernel_launch(void* const* d_in, const int* in_sizes, int n_in,
                              void* d_out, int out_size) {
    const float* images = (const float*)d_in[0];
    float* out = (float*)d_out;
    const int n_rows = in_sizes[0] / 8;      // 4,194,304 for the bench shape
    const int blocks = n_rows / 512;         // 512 rows per 256-thread block
    idct_54271206752953_kernel<<<blocks, 256>>>(images, out, n_rows);
}

// round 4
// speedup vs baseline: 1.2507x; 1.2507x over previous
#include <cuda_runtime.h>

// 8x8 IDCT: separable + even/odd symmetry, 2 block-rows per thread (MLP=4),
// ALL global access 128-bit (2 shfl-transposes per block-row).
//   out = 0.25 * M^T * S * M + 128,  M[y][v] = a[y]*cos((2v+1)*y*pi/16)
// R3 lesson: column-order scalar stores quadruple L1 store wavefronts and
// choke the LSU (L1=85%, DRAM=51%). This version keeps the MLP=4 loads but
// transposes back before storing so stores are STG.128.

#define FULLMASK 0xFFFFFFFFu

__device__ __forceinline__ void transpose8(float v[8], int r) {
    // 8x8 transpose across an 8-lane group, one row per lane; 3 bfly stages.
#pragma unroll
    for (int m = 1; m < 8; m <<= 1) {
#pragma unroll
        for (int i = 0; i < 8; i++) {
            if (i & m) continue;
            const int j = i | m;
            const bool up = (r & m) != 0;
            float send = up ? v[i] : v[j];
            float recv = __shfl_xor_sync(FULLMASK, send, m);
            if (up) v[i] = recv; else v[j] = recv;
        }
    }
}

// Even rows of M (y=0,2,4,6) and odd rows (y=1,3,5,7), columns v=0..3.
#define ME_ROWS \
    { 0.70710678f,  0.70710678f,  0.70710678f,  0.70710678f }, \
    { 0.92387953f,  0.38268343f, -0.38268343f, -0.92387953f }, \
    { 0.70710678f, -0.70710678f, -0.70710678f,  0.70710678f }, \
    { 0.38268343f, -0.92387953f,  0.92387953f, -0.38268343f }
#define MO_ROWS \
    { 0.98078528f,  0.83146961f,  0.55557023f,  0.19509032f }, \
    { 0.83146961f, -0.19509032f, -0.98078528f, -0.55557023f }, \
    { 0.55557023f, -0.98078528f,  0.19509032f,  0.83146961f }, \
    { 0.19509032f, -0.55557023f,  0.83146961f, -0.98078528f }

__device__ __forceinline__ void idct_row_pass(const float s[8], float acc[8]) {
    const float ME[4][4] = { ME_ROWS };
    const float MO[4][4] = { MO_ROWS };
#pragma unroll
    for (int v = 0; v < 4; v++) {
        float e = s[0] * ME[0][v];
        e = fmaf(s[2], ME[1][v], e);
        e = fmaf(s[4], ME[2][v], e);
        e = fmaf(s[6], ME[3][v], e);
        float o = s[1] * MO[0][v];
        o = fmaf(s[3], MO[1][v], o);
        o = fmaf(s[5], MO[2][v], o);
        o = fmaf(s[7], MO[3][v], o);
        acc[v]     = e + o;
        acc[7 - v] = e - o;
    }
}

__device__ __forceinline__ void idct_col_pass(const float acc[8], float o[8]) {
    const float ME[4][4] = { ME_ROWS };
    const float MO[4][4] = { MO_ROWS };
#pragma unroll
    for (int u = 0; u < 4; u++) {
        float e = fmaf(acc[0], 0.25f * ME[0][u], 128.0f);
        e = fmaf(acc[2], 0.25f * ME[1][u], e);
        e = fmaf(acc[4], 0.25f * ME[2][u], e);
        e = fmaf(acc[6], 0.25f * ME[3][u], e);
        float od = acc[1] * (0.25f * MO[0][u]);
        od = fmaf(acc[3], 0.25f * MO[1][u], od);
        od = fmaf(acc[5], 0.25f * MO[2][u], od);
        od = fmaf(acc[7], 0.25f * MO[3][u], od);
        o[u]     = e + od;
        o[7 - u] = e - od;
    }
}

__global__ void __launch_bounds__(256)
idct_54271206752953_kernel(const float* __restrict__ in,
                           float* __restrict__ out,
                           int n_rows) {
    const int tid = threadIdx.x;
    const int r = tid & 7;
    // Each 256-thread block owns 512 consecutive 8-float rows.
    const int base = blockIdx.x * 512;
    const int t0 = base + tid;
    const int t1 = base + 256 + tid;

    // Front-batch 4 independent LDG.128 (MLP = 4).
    const float4* in4 = reinterpret_cast<const float4*>(in);
    float4 a0 = in4[(size_t)t0 * 2 + 0];
    float4 a1 = in4[(size_t)t0 * 2 + 1];
    float4 b0 = in4[(size_t)t1 * 2 + 0];
    float4 b1 = in4[(size_t)t1 * 2 + 1];

    float sA[8] = { a0.x, a0.y, a0.z, a0.w, a1.x, a1.y, a1.z, a1.w };
    float sB[8] = { b0.x, b0.y, b0.z, b0.w, b1.x, b1.y, b1.z, b1.w };

    float accA[8], accB[8];
    idct_row_pass(sA, accA);
    idct_row_pass(sB, accB);

    // Two independent transpose chains; shfl latency overlaps.
    transpose8(accA, r);
    transpose8(accB, r);

    float oA[8], oB[8];
    idct_col_pass(accA, oA);
    idct_col_pass(accB, oB);

    // Transpose back to row order so stores are STG.128.
    transpose8(oA, r);
    transpose8(oB, r);

    float4* out4 = reinterpret_cast<float4*>(out);
    out4[(size_t)t0 * 2 + 0] = make_float4(oA[0], oA[1], oA[2], oA[3]);
    out4[(size_t)t0 * 2 + 1] = make_float4(oA[4], oA[5], oA[6], oA[7]);
    out4[(size_t)t1 * 2 + 0] = make_float4(oB[0], oB[1], oB[2], oB[3]);
    out4[(size_t)t1 * 2 + 1] = make_float4(oB[4], oB[5], oB[6], oB[7]);
}

extern "C" void kernel_launch(void* const* d_in, const int* in_sizes, int n_in,
                              void* d_out, int out_size) {
    const float* images = (const float*)d_in[0];
    float* out = (float*)d_out;
    const int n_rows = in_sizes[0] / 8;      // 4,194,304 for the bench shape
    const int blocks = n_rows / 512;         // 512 rows per 256-thread block
    idct_54271206752953_kernel<<<blocks, 256>>>(images, out, n_rows);
}